// round 3
// baseline (speedup 1.0000x reference)
#include <cuda_runtime.h>

// Shapes fixed by dataset: x:(64,16,128,2), log_delay:(256,1), log_weight scalar,
// noise:(16,128,256,2), out:(64,16,128,256) fp32.
#define T_DIM 64
#define N_DIM 16
#define C_DIM 128
#define D_DIM 256

// One 64-thread block per (n,c). Each thread owns 4 consecutive d -> float4
// stores. Per (thread, stream j) the 4 delays rd span <= 2, so all reads at
// time t come from a 3-wide sliding window z[B+t..B+t+2] kept in registers:
// 2 LDS per t (one per j) instead of 8. Window select via PRMT (no preds).
__global__ __launch_bounds__(64) void jeffress_kernel(
    const float* __restrict__ x,
    const float* __restrict__ log_delay,
    const float* __restrict__ log_weight,
    const float* __restrict__ noise,
    float* __restrict__ out)
{
    // x duplicated along t (+ pad) so (t - rd) mod 64 becomes base + t,
    // and window lookahead up to index B+66 (<= 130) stays in bounds.
    __shared__ float xs[2][132];
    __shared__ int maxd_sh[2];

    const int tid = threadIdx.x;       // 0..63
    const int nc  = blockIdx.x;        // 0..2047
    const int n   = nc >> 7;
    const int c   = nc & 127;
    const float w = expf(__ldg(log_weight));

    // ---- load x[t=tid] (both streams), pre-scaled by w, duplicated
    {
        const float2 v2 = *reinterpret_cast<const float2*>(
            x + (((size_t)tid * N_DIM + n) * C_DIM + c) * 2);
        float v0 = w * v2.x;
        float v1 = w * v2.y;
        xs[0][tid]      = v0;  xs[0][tid + 64] = v0;
        xs[1][tid]      = v1;  xs[1][tid + 64] = v1;
        if (tid < 4) { xs[0][tid + 128] = v0; xs[1][tid + 128] = v1; }
    }
    __syncthreads();

    // ---- argmax over t per stream (first-occurrence semantics)
    {
        const int wj   = tid >> 5;
        const int lane = tid & 31;
        float v1 = xs[wj][lane];
        float v2 = xs[wj][lane + 32];
        float v; int idx;
        if (v2 > v1) { v = v2; idx = lane + 32; } else { v = v1; idx = lane; }
        #pragma unroll
        for (int o = 16; o > 0; o >>= 1) {
            float ov = __shfl_xor_sync(0xffffffffu, v, o);
            int   oi = __shfl_xor_sync(0xffffffffu, idx, o);
            if (ov > v || (ov == v && oi < idx)) { v = ov; idx = oi; }
        }
        if (lane == 0) maxd_sh[wj] = (T_DIM - 1) - idx;
    }
    __syncthreads();

    const int d0  = tid << 2;
    const int md0 = maxd_sh[0];
    const int md1 = maxd_sh[1];

    // noise: 8 consecutive floats -> two float4 loads
    const float4* nzp = reinterpret_cast<const float4*>(
        noise + ((size_t)nc * D_DIM + d0) * 2);
    float4 nzA = __ldg(nzp);
    float4 nzB = __ldg(nzp + 1);
    float nz0[4] = {nzA.x, nzA.z, nzB.x, nzB.z};   // j = 0
    float nz1[4] = {nzA.y, nzA.w, nzB.y, nzB.w};   // j = 1

    // ---- delays (identical math to the bit-exact version)
    int rd0[4], rd1[4];
    #pragma unroll
    for (int i = 0; i < 4; i++) {
        int d = d0 + i;
        float s0 = 64.0f * expf(__ldg(log_delay + d));
        float s1 = 64.0f * expf(__ldg(log_delay + (D_DIM - 1 - d)));
        float f0 = floorf(s0), f1 = floorf(s1);
        int r0 = (int)f0 + ((nz0[i] < (s0 - f0)) ? 1 : 0);
        int r1 = (int)f1 + ((nz1[i] < (s1 - f1)) ? 1 : 0);
        rd0[i] = min(r0, md0);
        rd1[i] = min(r1, md1);
    }

    // ---- per-stream window base + PRMT select controls
    int rmax0 = max(max(rd0[0], rd0[1]), max(rd0[2], rd0[3]));
    int rmax1 = max(max(rd1[0], rd1[1]), max(rd1[2], rd1[3]));
    const float* pz0 = &xs[0][64 - rmax0];   // window: pz[t], pz[t+1], pz[t+2]
    const float* pz1 = &xs[1][64 - rmax1];

    unsigned ca0[4], cb0[4], ca1[4], cb1[4];
    #pragma unroll
    for (int i = 0; i < 4; i++) {
        int o0 = min(rmax0 - rd0[i], 2);     // value = window[o], o in {0,1,2}
        int o1 = min(rmax1 - rd1[i], 2);
        ca0[i] = (o0 == 0) ? 0x3210u : 0x7654u;   // pick w0 vs w1
        cb0[i] = (o0 == 2) ? 0x7654u : 0x3210u;   // then pick w2 vs that
        ca1[i] = (o1 == 0) ? 0x3210u : 0x7654u;
        cb1[i] = (o1 == 2) ? 0x7654u : 0x3210u;
    }

    // init windows
    unsigned wa0 = __float_as_uint(pz0[0]);
    unsigned wa1 = __float_as_uint(pz0[1]);
    unsigned wa2 = __float_as_uint(pz0[2]);
    unsigned wb0 = __float_as_uint(pz1[0]);
    unsigned wb1 = __float_as_uint(pz1[1]);
    unsigned wb2 = __float_as_uint(pz1[2]);

    float y0[4] = {0.f, 0.f, 0.f, 0.f};
    float y1[4] = {0.f, 0.f, 0.f, 0.f};
    float4* outp = reinterpret_cast<float4*>(out + (size_t)nc * D_DIM + d0);
    const size_t tstride4 = (size_t)N_DIM * C_DIM * D_DIM / 4;

    #pragma unroll 4
    for (int t = 0; t < T_DIM; t++) {
        float4 v;
        #pragma unroll
        for (int i = 0; i < 4; i++) {
            unsigned u0 = __byte_perm(wa0, wa1, ca0[i]);
            u0 = __byte_perm(u0, wa2, cb0[i]);
            unsigned u1 = __byte_perm(wb0, wb1, ca1[i]);
            u1 = __byte_perm(u1, wb2, cb1[i]);
            y0[i] = y0[i] * 0.5f + __uint_as_float(u0);
            y1[i] = y1[i] * 0.5f + __uint_as_float(u1);
        }
        v.x = y0[0] + y1[0];
        v.y = y0[1] + y1[1];
        v.z = y0[2] + y1[2];
        v.w = y0[3] + y1[3];
        *outp = v;
        outp += tstride4;

        // slide windows (pad guarantees in-bounds even at t=63)
        wa0 = wa1; wa1 = wa2; wa2 = __float_as_uint(pz0[t + 3]);
        wb0 = wb1; wb1 = wb2; wb2 = __float_as_uint(pz1[t + 3]);
    }
}

extern "C" void kernel_launch(void* const* d_in, const int* in_sizes, int n_in,
                              void* d_out, int out_size) {
    const float* x          = (const float*)d_in[0];
    const float* log_delay  = (const float*)d_in[1];
    const float* log_weight = (const float*)d_in[2];
    const float* noise      = (const float*)d_in[3];
    float* out = (float*)d_out;

    jeffress_kernel<<<N_DIM * C_DIM, 64>>>(x, log_delay, log_weight, noise, out);
}

// round 4
// speedup vs baseline: 1.0012x; 1.0012x over previous
#include <cuda_runtime.h>

// Shapes fixed by dataset: x:(64,16,128,2), log_delay:(256,1), log_weight scalar,
// noise:(16,128,256,2), out:(64,16,128,256) fp32.
#define T_DIM 64
#define N_DIM 16
#define C_DIM 128
#define D_DIM 256

// One 128-thread block per (n,c) pair -> 2048 blocks, 16 blocks/SM resident,
// ~55 warps/SM. Each thread owns 2 consecutive d -> float2 streaming stores
// (evict-first: output is write-once, keep it out of L2).
__global__ __launch_bounds__(128) void jeffress_kernel(
    const float* __restrict__ x,
    const float* __restrict__ log_delay,
    const float* __restrict__ log_weight,
    const float* __restrict__ noise,
    float* __restrict__ out)
{
    // x duplicated along t so (t - rd) mod 64 becomes base + t.
    __shared__ float xs[2][128];
    __shared__ int maxd_sh[2];

    const int tid = threadIdx.x;       // 0..127
    const int nc  = blockIdx.x;        // 0..2047
    const int n   = nc >> 7;
    const int c   = nc & 127;
    const float w = expf(__ldg(log_weight));

    // ---- load x[t] (both streams), pre-scaled by w, duplicated for wrap
    if (tid < 64) {
        const float2 v2 = *reinterpret_cast<const float2*>(
            x + (((size_t)tid * N_DIM + n) * C_DIM + c) * 2);
        float v0 = w * v2.x;
        float v1 = w * v2.y;
        xs[0][tid]      = v0;  xs[0][tid + 64] = v0;
        xs[1][tid]      = v1;  xs[1][tid + 64] = v1;
    }
    __syncthreads();

    // ---- argmax over t per stream j (warps 0 and 1), first-occurrence wins
    if (tid < 64) {
        const int wj   = tid >> 5;
        const int lane = tid & 31;
        float v1 = xs[wj][lane];
        float v2 = xs[wj][lane + 32];
        float v; int idx;
        if (v2 > v1) { v = v2; idx = lane + 32; } else { v = v1; idx = lane; }
        #pragma unroll
        for (int o = 16; o > 0; o >>= 1) {
            float ov = __shfl_xor_sync(0xffffffffu, v, o);
            int   oi = __shfl_xor_sync(0xffffffffu, idx, o);
            if (ov > v || (ov == v && oi < idx)) { v = ov; idx = oi; }
        }
        if (lane == 0) maxd_sh[wj] = (T_DIM - 1) - idx;
    }
    __syncthreads();

    const int d0  = tid << 1;          // 2 consecutive d per thread
    const int md0 = maxd_sh[0];
    const int md1 = maxd_sh[1];

    // noise[(nc*256 + d)*2 + j]: 4 consecutive floats -> one float4 load
    const float4 nz = __ldg(reinterpret_cast<const float4*>(
        noise + ((size_t)nc * D_DIM + d0) * 2));
    float nz0[2] = {nz.x, nz.z};   // j = 0
    float nz1[2] = {nz.y, nz.w};   // j = 1

    // ---- per-(d, stream) delays -> base pointers into the duplicated array
    const float* b0[2];
    const float* b1[2];
    #pragma unroll
    for (int i = 0; i < 2; i++) {
        int d = d0 + i;
        float s0 = 64.0f * expf(__ldg(log_delay + d));
        float s1 = 64.0f * expf(__ldg(log_delay + (D_DIM - 1 - d)));  // flip
        float f0 = floorf(s0), f1 = floorf(s1);
        int r0 = (int)f0 + ((nz0[i] < (s0 - f0)) ? 1 : 0);
        int r1 = (int)f1 + ((nz1[i] < (s1 - f1)) ? 1 : 0);
        int rd0 = min(r0, md0);
        int rd1 = min(r1, md1);
        b0[i] = &xs[0][64 - rd0];      // b[t] == x[(t - rd) mod 64]
        b1[i] = &xs[1][64 - rd1];
    }

    // ---- main scan: y_t = 0.5*y_{t-1} + x_shifted, out = y(j=0)+y(j=1)
    float y0[2] = {0.f, 0.f};
    float y1[2] = {0.f, 0.f};
    float2* outp = reinterpret_cast<float2*>(out + (size_t)nc * D_DIM + d0);
    const size_t tstride2 = (size_t)N_DIM * C_DIM * D_DIM / 2;

    #pragma unroll 8
    for (int t = 0; t < T_DIM; t++) {
        float2 v;
        #pragma unroll
        for (int i = 0; i < 2; i++) {
            y0[i] = y0[i] * 0.5f + b0[i][t];
            y1[i] = y1[i] * 0.5f + b1[i][t];
        }
        v.x = y0[0] + y1[0];
        v.y = y0[1] + y1[1];
        __stcs(outp, v);               // streaming store: evict-first
        outp += tstride2;
    }
}

extern "C" void kernel_launch(void* const* d_in, const int* in_sizes, int n_in,
                              void* d_out, int out_size) {
    const float* x          = (const float*)d_in[0];
    const float* log_delay  = (const float*)d_in[1];
    const float* log_weight = (const float*)d_in[2];
    const float* noise      = (const float*)d_in[3];
    float* out = (float*)d_out;

    jeffress_kernel<<<N_DIM * C_DIM, 128>>>(x, log_delay, log_weight, noise, out);
}